// round 17
// baseline (speedup 1.0000x reference)
#include <cuda_runtime.h>

// Soft-DTW, gamma = 0.01, p = 2, B = 64, M = N = 512.
// One CTA per batch; 256 threads; thread jj owns columns colA=2jj, colB=2jj+1.
// R9-proven dataflow and instruction ORDER; this revision only removes
// instructions (no reordering):
//   - mailbox rows padded to 640 slots (+64 offset), tail prefilled valid ->
//     single fused loop, no index clamps, publish guarded by isPub only
//   - ysh padded +-64/80 -> no clamp on the y prefetch
// At local step t (global s = t + 64w): A = (iiA = t - 2*lane, colA),
// B = (iiA - 1, colB). B deps all-register; A deps via shfl / mailbox.

#define BIG   1e30f
#define KEXP  144.26950408889634f    // 100 * log2(e)
#define GLN2  0.006931471805599453f  // 0.01 * ln(2)

__device__ __forceinline__ float ex2f_(float v) {
    float r; asm("ex2.approx.ftz.f32 %0, %1;" : "=f"(r) : "f"(v)); return r;
}
__device__ __forceinline__ float lg2f_(float v) {
    float r; asm("lg2.approx.ftz.f32 %0, %1;" : "=f"(r) : "f"(v)); return r;
}

// softmin3 = m - gamma*ln(1 + e^{(m-v1)/g} + e^{(m-v2)/g})  (proven numerics)
__device__ __forceinline__ float softmin3(float dg, float up, float lf) {
    float t1 = fminf(dg, up);
    float t2 = fmaxf(dg, up);
    float m  = fminf(t1, lf);
    float u  = fmaxf(t1, lf);
    float mk = m * KEXP;
    float a1 = fmaf(-KEXP, t2, mk);
    float a2 = fmaf(-KEXP, u,  mk);
    float ss = 1.0f + ex2f_(a1) + ex2f_(a2);
    return fmaf(-GLN2, lg2f_(ss), m);
}

__device__ __forceinline__ uint2 lds_v2_vol(const uint2* p) {
    uint2 r; unsigned a = (unsigned)__cvta_generic_to_shared(p);
    asm volatile("ld.volatile.shared.v2.u32 {%0,%1}, [%2];"
                 : "=r"(r.x), "=r"(r.y) : "r"(a));
    return r;
}
__device__ __forceinline__ void sts_v2_vol(uint2* p, unsigned vx, unsigned vy) {
    unsigned a = (unsigned)__cvta_generic_to_shared(p);
    asm volatile("st.volatile.shared.v2.u32 [%0], {%1,%2};"
                 :: "r"(a), "r"(vx), "r"(vy) : "memory");
}
// Verify prefetched mailbox entry {pre.x=valBits, pre.y=tag} against tag t;
// reload (rare) until the tag matches. Warp-uniform slot => uniform branches.
__device__ __forceinline__ float mb_verify(const uint2* slot, unsigned t, uint2& pre) {
    unsigned a = (unsigned)__cvta_generic_to_shared(slot);
    asm volatile("{\n\t"
        ".reg .pred p;\n\t"
        "setp.eq.u32 p, %1, %2;\n\t"
        "@p bra D%=;\n\t"
        "R%=:\n\t"
        "ld.volatile.shared.v2.u32 {%0,%1}, [%3];\n\t"
        "setp.ne.u32 p, %1, %2;\n\t"
        "@p bra R%=;\n\t"
        "D%=:\n\t"
        "}"
        : "+r"(pre.x), "+r"(pre.y) : "r"(t), "r"(a) : "memory");
    return __uint_as_float(pre.x);
}

__global__ __launch_bounds__(256, 1)
void softdtw_kernel(const float* __restrict__ x,
                    const float* __restrict__ y,
                    float* __restrict__ out)
{
    __shared__ float yshp_raw[656];  // logical rows [-64, 592), offset +64
    __shared__ uint2 bnd[8][640];    // slot k holds row k-64; rows 0..6 real, 7 dummy

    const int b    = blockIdx.x;
    const int jj   = threadIdx.x;          // 0..255
    const int w    = jj >> 5;
    const int lane = jj & 31;
    const int colA = 2 * jj;
    const int colB = colA + 1;
    float* yshp = yshp_raw + 64;

    yshp[colA] = y[b * 512 + colA];
    yshp[colB] = y[b * 512 + colB];
    const float xA = x[b * 512 + colA];
    const float xB = x[b * 512 + colB];
    if (jj < 64) yshp_raw[jj] = 0.0f;                    // rows [-64, 0)
    if (jj < 80) yshp_raw[576 + jj] = 0.0f;              // rows [512, 592)

    // mailboxes: poison writable slots [0,576) of rows 0..6; prefill tail
    // slots [576,640) of rows 0..6 and ALL of dummy row 7 with {BIG, tag=slot-64}
    for (int s = jj; s < 7 * 576; s += 256) {
        int r = s / 576, k = s - r * 576;
        bnd[r][k].y = 0xFFFFFFFFu;
    }
    for (int s = jj; s < 7 * 64; s += 256) {
        int r = s >> 6, k = (s & 63) + 576;
        bnd[r][k] = make_uint2(__float_as_uint(BIG), (unsigned)(k - 64));
    }
    for (int t = jj; t < 640; t += 256)
        bnd[7][t] = make_uint2(__float_as_uint(BIG), (unsigned)(t - 64));
    __syncthreads();                        // the only full barrier

    const uint2* mrow = bnd[(w + 7) & 7];   // w=0 -> dummy row 7; else bnd[w-1]
    uint2*       prow = bnd[w & 7];         // producer row (used only if w<7)
    const bool   isPub = (lane == 31) && (w < 7);

    float aPrev  = BIG;                     // A(t-1)
    float aPrev2 = BIG;                     // A(t-2)
    float bPrev  = BIG;                     // B(t-1)
    float nbPrev = (jj == 0) ? 0.0f : BIG;  // neighbor B(t-2); R[-1,-1]=0 seed

    float yA = yshp[-2 * lane];             // ysh[iiA] at t=0 (pad if negative)
    float yB = yshp[-2 * lane - 1];         // ysh[iiA-1]

    uint2 pre = lds_v2_vol(&mrow[64]);      // prefetch slot for t=0

    // ---- fused main loop: t = 0..574 (R9 instruction order) ----
    #pragma unroll 2
    for (int t = 0; t < 575; ++t) {
        const int iiA  = t - 2 * lane;
        const int rowB = iiA - 1;

        float nbCur = __shfl_up_sync(0xffffffffu, bPrev, 1);

        // B cell first: register-only deps, hides mailbox latency
        float dB = xB - yB;
        float rB = fmaf(dB, dB, softmin3(aPrev2, bPrev, aPrev));
        rB = ((unsigned)rowB < 512u) ? rB : BIG;

        // publish ASAP to feed the downstream warp (padded row: no bounds check)
        if (isPub)
            sts_v2_vol(&prow[rowB + 64], __float_as_uint(rB), (unsigned)rowB);

        // mailbox value for lane 0 (uniform slot/tag across the warp)
        float mv = mb_verify(&mrow[t + 64], (unsigned)t, pre);
        if (lane == 0) nbCur = mv;

        // A cell
        float dA = xA - yA;
        float rA = fmaf(dA, dA, softmin3(nbPrev, aPrev, nbCur));
        rA = ((unsigned)iiA < 512u) ? rA : BIG;

        // rotate state
        aPrev2 = aPrev;  aPrev = rA;  bPrev = rB;  nbPrev = nbCur;
        yB = yA;
        yA = yshp[iiA + 1];                 // padded: no clamp

        pre = lds_v2_vol(&mrow[t + 65]);    // prefetch next slot (<= 639)
    }

    if (jj == 255) out[b] = bPrev;          // rB at t=574, rowB=511 -> R[511,511]
}

extern "C" void kernel_launch(void* const* d_in, const int* in_sizes, int n_in,
                              void* d_out, int out_size)
{
    const float* x = (const float*)d_in[0];
    const float* y = (const float*)d_in[1];
    float* out = (float*)d_out;
    softdtw_kernel<<<64, 256>>>(x, y, out);
}